// round 4
// baseline (speedup 1.0000x reference)
#include <cuda_runtime.h>
#include <cuda_fp16.h>

#define NMAX 4096
#define SMAX 32
#define DDIM 128
#define GSZ  8
#define CAP  4500000u
#define VLD  4224
#define EPSK 1e-6f
#define ITS  20

// ---------------- static device scratch (allocation-free) ----------------
__device__ float  g_Xt[(size_t)SMAX*NMAX*DDIM];   // 64MB gathered treated
__device__ float  g_Xc[(size_t)SMAX*NMAX*DDIM];   // 64MB gathered control
__device__ float  g_nrmT[SMAX*NMAX];
__device__ float  g_nrmC[SMAX*NMAX];
__device__ __half g_Km[(size_t)GSZ*CAP];          // 72MB  K (fp16), augmented+padded
__device__ float  g_Mm[(size_t)GSZ*CAP];          // 144MB M (fp32), augmented
__device__ float  g_y[GSZ*VLD];
__device__ float  g_z[GSZ*VLD];
__device__ int    g_it[NMAX], g_ic[NMAX];
__device__ int    g_nt, g_nc, g_ld;
__device__ float  g_a0, g_an, g_b0, g_bn;
__device__ float  g_psum[SMAX*1024];
__device__ float  g_pmax[SMAX*1024];
__device__ float  g_sumv[SMAX], g_maxv[SMAX];
__device__ float  g_cpart[SMAX*129];

// ---------------- partition: scan t, index lists + scalars ----------------
__global__ void partition_k(const int* __restrict__ t) {
    __shared__ int cnt[256];
    const int tid = threadIdx.x;
    const int base = tid * 16;
    int c = 0;
    #pragma unroll
    for (int k = 0; k < 16; k++) c += (t[base + k] > 0);
    cnt[tid] = c;
    __syncthreads();
    for (int off = 1; off < 256; off <<= 1) {
        int v = (tid >= off) ? cnt[tid - off] : 0;
        __syncthreads();
        cnt[tid] += v;
        __syncthreads();
    }
    const int nt = cnt[255];
    int tp = cnt[tid] - c;                 // exclusive prefix of treated
    for (int k = 0; k < 16; k++) {
        int idx = base + k;
        if (t[idx] > 0) { g_it[tp] = idx; tp++; }
        else            { g_ic[idx - tp] = idx; }
    }
    if (!tid) {
        int nc = NMAX - nt;
        g_nt = nt; g_nc = nc;
        g_ld = ((nc + 1 + 63) >> 6) << 6;  // 128B-aligned half rows
        float p = (float)nt / (float)NMAX;
        g_a0 = p / (float)nt;       g_an = 1.0f - p;
        g_b0 = (1.0f - p) / (float)nc; g_bn = p;
    }
}

// ---------------- gather rows (one thread per output element) ----------------
__global__ void gather_k(const float* __restrict__ X) {
    size_t idx = (size_t)blockIdx.x * 256 + threadIdx.x;   // over SMAX*NMAX*DDIM
    int d = (int)(idx & 127);
    int r = (int)((idx >> 7) & 4095);
    int s = (int)(idx >> 19);
    if (r < g_nt) g_Xt[idx] = X[(((size_t)g_it[r]) * SMAX + s) * DDIM + d];
    if (r < g_nc) g_Xc[idx] = X[(((size_t)g_ic[r]) * SMAX + s) * DDIM + d];
}

// ---------------- squared row norms (one warp per row) ----------------
__global__ void norms_k() {
    const int gidx = blockIdx.x * 8 + (threadIdx.x >> 5);
    const int lane = threadIdx.x & 31;
    const int s = gidx >> 12, r = gidx & 4095;
    if (r < g_nt) {
        float4 v = *(const float4*)(g_Xt + ((size_t)s * NMAX + r) * DDIM + lane * 4);
        float sq = v.x*v.x + v.y*v.y + v.z*v.z + v.w*v.w;
        #pragma unroll
        for (int o = 16; o; o >>= 1) sq += __shfl_down_sync(~0u, sq, o);
        if (!lane) g_nrmT[s * NMAX + r] = sq;
    }
    if (r < g_nc) {
        float4 v = *(const float4*)(g_Xc + ((size_t)s * NMAX + r) * DDIM + lane * 4);
        float sq = v.x*v.x + v.y*v.y + v.z*v.z + v.w*v.w;
        #pragma unroll
        for (int o = 16; o; o >>= 1) sq += __shfl_down_sync(~0u, sq, o);
        if (!lane) g_nrmC[s * NMAX + r] = sq;
    }
}

// ---------------- GEMM: M = nt + nc - 2 Xt Xc^T, with per-block max/sum partials --------
__global__ __launch_bounds__(256) void gemm_k(int g0) {
    const int nt = g_nt, nc = g_nc, ld = g_ld;
    const int by = blockIdx.y, bx = blockIdx.x, gz = blockIdx.z;
    const int s = g0 + gz;
    const int tid = threadIdx.x;
    if (by * 128 >= nt || bx * 128 >= nc) {
        if (!tid) { g_psum[s*1024 + by*32 + bx] = 0.f; g_pmax[s*1024 + by*32 + bx] = 0.f; }
        return;
    }
    const float* A = g_Xt + ((size_t)s * NMAX + by * 128) * DDIM;
    const float* B = g_Xc + ((size_t)s * NMAX + bx * 128) * DDIM;
    __shared__ float As[32][132];
    __shared__ float Bs[32][132];
    const int tx = tid & 15, ty = tid >> 4;
    float acc[8][8];
    #pragma unroll
    for (int i = 0; i < 8; i++)
        #pragma unroll
        for (int j = 0; j < 8; j++) acc[i][j] = 0.f;

    for (int k0 = 0; k0 < DDIM; k0 += 32) {
        __syncthreads();
        #pragma unroll
        for (int l = 0; l < 4; l++) {
            int fv = l * 256 + tid, r = fv >> 3, kv = fv & 7;
            float4 va = *(const float4*)(A + (size_t)r * DDIM + k0 + kv * 4);
            As[kv*4+0][r] = va.x; As[kv*4+1][r] = va.y; As[kv*4+2][r] = va.z; As[kv*4+3][r] = va.w;
            float4 vb = *(const float4*)(B + (size_t)r * DDIM + k0 + kv * 4);
            Bs[kv*4+0][r] = vb.x; Bs[kv*4+1][r] = vb.y; Bs[kv*4+2][r] = vb.z; Bs[kv*4+3][r] = vb.w;
        }
        __syncthreads();
        #pragma unroll
        for (int kk = 0; kk < 32; kk++) {
            float av[8], bv[8];
            *(float4*)av       = *(const float4*)&As[kk][ty * 4];
            *(float4*)(av + 4) = *(const float4*)&As[kk][64 + ty * 4];
            *(float4*)bv       = *(const float4*)&Bs[kk][tx * 4];
            *(float4*)(bv + 4) = *(const float4*)&Bs[kk][64 + tx * 4];
            #pragma unroll
            for (int i = 0; i < 8; i++)
                #pragma unroll
                for (int j = 0; j < 8; j++) acc[i][j] = fmaf(av[i], bv[j], acc[i][j]);
        }
    }

    float* Mp = g_Mm + (size_t)gz * CAP;
    float lmax = 0.f, lsum = 0.f;
    #pragma unroll
    for (int ri = 0; ri < 8; ri++) {
        int r = by * 128 + ((ri < 4) ? ty * 4 + ri : 64 + ty * 4 + (ri - 4));
        if (r >= nt) continue;
        float nr = g_nrmT[s * NMAX + r];
        #pragma unroll
        for (int q = 0; q < 2; q++) {
            int cb = bx * 128 + q * 64 + tx * 4;
            float m[4];
            #pragma unroll
            for (int e = 0; e < 4; e++) m[e] = fmaf(-2.f, acc[ri][q*4+e], nr + g_nrmC[s*NMAX + cb + e]);
            if (cb + 3 < nc) {
                *(float4*)(Mp + (size_t)r * ld + cb) = make_float4(m[0], m[1], m[2], m[3]);
                lmax = fmaxf(lmax, fmaxf(fmaxf(m[0], m[1]), fmaxf(m[2], m[3])));
                lsum += (m[0] + m[1]) + (m[2] + m[3]);
            } else {
                #pragma unroll
                for (int e = 0; e < 4; e++) if (cb + e < nc) {
                    Mp[(size_t)r * ld + cb + e] = m[e];
                    lmax = fmaxf(lmax, m[e]); lsum += m[e];
                }
            }
        }
    }
    #pragma unroll
    for (int o = 16; o; o >>= 1) {
        lmax = fmaxf(lmax, __shfl_down_sync(~0u, lmax, o));
        lsum += __shfl_down_sync(~0u, lsum, o);
    }
    __shared__ float rmx[8], rsm[8];
    if (!(tid & 31)) { rmx[tid >> 5] = lmax; rsm[tid >> 5] = lsum; }
    __syncthreads();
    if (!tid) {
        float mx = rmx[0], sm = rsm[0];
        #pragma unroll
        for (int w = 1; w < 8; w++) { mx = fmaxf(mx, rmx[w]); sm += rsm[w]; }
        g_pmax[s*1024 + by*32 + bx] = mx;
        g_psum[s*1024 + by*32 + bx] = sm;
    }
}

// ---------------- deterministic reduce of per-block partials ----------------
__global__ void reduce_k(int g0) {
    const int s = g0 + blockIdx.x, tid = threadIdx.x;
    __shared__ float ss[256], sm[256];
    float a = 0.f, m = 0.f;
    for (int k = tid; k < 1024; k += 256) { a += g_psum[s*1024 + k]; m = fmaxf(m, g_pmax[s*1024 + k]); }
    ss[tid] = a; sm[tid] = m;
    __syncthreads();
    for (int o = 128; o; o >>= 1) {
        if (tid < o) { ss[tid] += ss[tid + o]; sm[tid] = fmaxf(sm[tid], sm[tid + o]); }
        __syncthreads();
    }
    if (!tid) { g_sumv[s] = ss[0]; g_maxv[s] = sm[0]; }
}

// ---------------- build K = exp(-el*Mt)+eps (fp16), augment M, init z=1 -------
__global__ void kbuild_k(int g0) {
    const int nt = g_nt, nc = g_nc, ld = g_ld;
    const int i = blockIdx.x;
    if (i > nt) return;
    const int g = blockIdx.y, s = g0 + g, tid = threadIdx.x;
    const float delta = g_maxv[s];
    const float el = ((float)nt * (float)nc) / g_sumv[s];   // lam=1 / mean(M)
    const float Kd = __expf(-el * delta) + EPSK;
    __half* Kp = g_Km + (size_t)g * CAP + (size_t)i * ld;
    float*  Mp = g_Mm + (size_t)g * CAP + (size_t)i * ld;
    if (i < nt) {
        for (int j = tid; j < ld; j += 256) {
            float kv;
            if (j < nc)       kv = __expf(-el * Mp[j]) + EPSK;
            else if (j == nc) { kv = Kd; Mp[j] = delta; }
            else              kv = 0.f;
            Kp[j] = __float2half(kv);
        }
    } else {
        for (int j = tid; j < ld; j += 256) {
            float kv;
            if (j < nc)       { kv = Kd; Mp[j] = delta; }
            else if (j == nc) { kv = 1.0f + EPSK; Mp[j] = 0.f; }
            else              kv = 0.f;
            Kp[j] = __float2half(kv);
        }
    }
    if (!tid) g_z[g * VLD + i] = 1.0f;   // first u = a / 1 = a
}

// ---------------- y = K^T u, u = a / z  (column-parallel) ----------------
__global__ __launch_bounds__(256) void spmvA_k(int g0) {
    const int nt = g_nt, nc = g_nc, ld = g_ld;
    const int j0 = blockIdx.x * 128;
    if (j0 > nc) return;
    const int g = blockIdx.y, tid = threadIdx.x;
    __shared__ float us[NMAX + 1];
    __shared__ float red[16 * 128];
    const float a0 = g_a0, an = g_an;
    const float* zp = g_z + g * VLD;
    for (int i = tid; i <= nt; i += 256) us[i] = ((i < nt) ? a0 : an) / zp[i];
    __syncthreads();
    const int cg = tid & 15, ph = tid >> 4;
    const __half* Kp = g_Km + (size_t)g * CAP + j0 + cg * 8;
    float acc[8];
    #pragma unroll
    for (int k = 0; k < 8; k++) acc[k] = 0.f;
    #pragma unroll 4
    for (int i = ph; i <= nt; i += 16) {
        uint4 kv = *(const uint4*)(Kp + (size_t)i * ld);
        float u = us[i];
        const __half2* h = (const __half2*)&kv;
        float2 f;
        f = __half22float2(h[0]); acc[0] = fmaf(f.x, u, acc[0]); acc[1] = fmaf(f.y, u, acc[1]);
        f = __half22float2(h[1]); acc[2] = fmaf(f.x, u, acc[2]); acc[3] = fmaf(f.y, u, acc[3]);
        f = __half22float2(h[2]); acc[4] = fmaf(f.x, u, acc[4]); acc[5] = fmaf(f.y, u, acc[5]);
        f = __half22float2(h[3]); acc[6] = fmaf(f.x, u, acc[6]); acc[7] = fmaf(f.y, u, acc[7]);
    }
    #pragma unroll
    for (int k = 0; k < 8; k++) red[ph * 128 + cg * 8 + k] = acc[k];
    __syncthreads();
    if (tid < 128) {
        float y = 0.f;
        #pragma unroll
        for (int p = 0; p < 16; p++) y += red[p * 128 + tid];
        int j = j0 + tid;
        if (j <= nc) g_y[g * VLD + j] = y;
    }
}

// ---------------- z = K w, w = b / y  (row-parallel, 32 rows/block) ----------
__global__ __launch_bounds__(256) void spmvB_k(int g0) {
    const int nt = g_nt, nc = g_nc, ld = g_ld;
    const int bx = blockIdx.x, g = blockIdx.y, tid = threadIdx.x;
    const int i0 = bx * 32;
    if (i0 > nt) return;
    __shared__ __align__(16) float ws[VLD];
    const float b0 = g_b0, bn = g_bn;
    const float* yp = g_y + g * VLD;
    for (int j = tid; j < ld; j += 256) {
        float w = 0.f;
        if (j <= nc) w = ((j < nc) ? b0 : bn) / yp[j];
        ws[j] = w;
    }
    __syncthreads();
    const int lane = tid & 31, wid = tid >> 5;
    for (int rr = 0; rr < 4; rr++) {
        int row = i0 + wid * 4 + rr;
        if (row > nt) break;
        const __half* Kp = g_Km + (size_t)g * CAP + (size_t)row * ld;
        float acc = 0.f;
        #pragma unroll 2
        for (int jb = lane * 8; jb < ld; jb += 256) {
            uint4 kv = *(const uint4*)(Kp + jb);
            float4 w0 = *(const float4*)(ws + jb);
            float4 w1 = *(const float4*)(ws + jb + 4);
            const __half2* h = (const __half2*)&kv;
            float2 f;
            f = __half22float2(h[0]); acc = fmaf(f.x, w0.x, acc); acc = fmaf(f.y, w0.y, acc);
            f = __half22float2(h[1]); acc = fmaf(f.x, w0.z, acc); acc = fmaf(f.y, w0.w, acc);
            f = __half22float2(h[2]); acc = fmaf(f.x, w1.x, acc); acc = fmaf(f.y, w1.y, acc);
            f = __half22float2(h[3]); acc = fmaf(f.x, w1.z, acc); acc = fmaf(f.y, w1.w, acc);
        }
        #pragma unroll
        for (int o = 16; o; o >>= 1) acc += __shfl_down_sync(~0u, acc, o);
        if (!lane) g_z[g * VLD + row] = acc;
    }
}

// ---------------- partial = sum_ij u_i v_j K_ij Mt_ij  ----------------
__global__ __launch_bounds__(256) void contract_k(int g0) {
    const int nt = g_nt, nc = g_nc, ld = g_ld;
    const int bx = blockIdx.x, g = blockIdx.y;
    const int s = g0 + g, tid = threadIdx.x;
    const int i0 = bx * 32;
    if (i0 > nt) { if (!tid) g_cpart[s * 129 + bx] = 0.f; return; }
    __shared__ __align__(16) float ws[VLD];
    __shared__ float wp[8];
    const float b0 = g_b0, bn = g_bn, a0 = g_a0, an = g_an;
    const float* yp = g_y + g * VLD;
    for (int j = tid; j < ld; j += 256) {
        float w = 0.f;
        if (j <= nc) w = ((j < nc) ? b0 : bn) / yp[j];
        ws[j] = w;
    }
    __syncthreads();
    const int lane = tid & 31, wid = tid >> 5;
    float wsum = 0.f;
    for (int rr = 0; rr < 4; rr++) {
        int row = i0 + wid * 4 + rr;
        if (row > nt) break;
        const __half* Kp = g_Km + (size_t)g * CAP + (size_t)row * ld;
        const float*  Mp = g_Mm + (size_t)g * CAP + (size_t)row * ld;
        float acc = 0.f;
        for (int jb = lane * 8; jb < ld; jb += 256) {
            uint4 kv = *(const uint4*)(Kp + jb);
            float4 m0 = *(const float4*)(Mp + jb);
            float4 m1 = *(const float4*)(Mp + jb + 4);
            float4 w0 = *(const float4*)(ws + jb);
            float4 w1 = *(const float4*)(ws + jb + 4);
            const __half2* h = (const __half2*)&kv;
            float2 f;
            f = __half22float2(h[0]); acc = fmaf(f.x * m0.x, w0.x, acc); acc = fmaf(f.y * m0.y, w0.y, acc);
            f = __half22float2(h[1]); acc = fmaf(f.x * m0.z, w0.z, acc); acc = fmaf(f.y * m0.w, w0.w, acc);
            f = __half22float2(h[2]); acc = fmaf(f.x * m1.x, w1.x, acc); acc = fmaf(f.y * m1.y, w1.y, acc);
            f = __half22float2(h[3]); acc = fmaf(f.x * m1.z, w1.z, acc); acc = fmaf(f.y * m1.w, w1.w, acc);
        }
        #pragma unroll
        for (int o = 16; o; o >>= 1) acc += __shfl_down_sync(~0u, acc, o);
        if (!lane) {
            float u = ((row < nt) ? a0 : an) / g_z[g * VLD + row];
            wsum += u * acc;
        }
    }
    if (!lane) wp[wid] = wsum;
    __syncthreads();
    if (!tid) {
        float t2 = 0.f;
        #pragma unroll
        for (int w = 0; w < 8; w++) t2 += wp[w];
        g_cpart[s * 129 + bx] = t2;
    }
}

// ---------------- final deterministic sum -> d_out ----------------
__global__ void final_k(float* __restrict__ out) {
    __shared__ float ss[256];
    const int tid = threadIdx.x;
    float a = 0.f;
    for (int k = tid; k < SMAX * 129; k += 256) a += g_cpart[k];
    ss[tid] = a;
    __syncthreads();
    for (int o = 128; o; o >>= 1) { if (tid < o) ss[tid] += ss[tid + o]; __syncthreads(); }
    if (!tid) out[0] = 2.0f * ss[0];
}

extern "C" void kernel_launch(void* const* d_in, const int* in_sizes, int n_in,
                              void* d_out, int out_size) {
    (void)in_sizes; (void)n_in; (void)out_size;
    const float* X = (const float*)d_in[0];
    const int*   t = (const int*)d_in[1];

    partition_k<<<1, 256>>>(t);
    gather_k<<<(SMAX * NMAX * DDIM) / 256, 256>>>(X);
    norms_k<<<(SMAX * NMAX) / 8, 256>>>();

    for (int g0 = 0; g0 < SMAX; g0 += GSZ) {
        gemm_k<<<dim3(32, 32, GSZ), 256>>>(g0);
        reduce_k<<<GSZ, 256>>>(g0);
        kbuild_k<<<dim3(NMAX + 1, GSZ), 256>>>(g0);
        for (int it = 0; it < ITS; ++it) {
            spmvA_k<<<dim3(33, GSZ), 256>>>(g0);
            spmvB_k<<<dim3(129, GSZ), 256>>>(g0);
        }
        spmvA_k<<<dim3(33, GSZ), 256>>>(g0);   // y for v = b/(K^T u_final)
        contract_k<<<dim3(129, GSZ), 256>>>(g0);
    }
    final_k<<<1, 256>>>((float*)d_out);
}

// round 5
// speedup vs baseline: 1.0157x; 1.0157x over previous
#include <cuda_runtime.h>
#include <cuda_fp16.h>

#define NMAX 4096
#define SMAX 32
#define DDIM 128
#define GSZ  32
#define CAP  4500000u
#define VLD  4224
#define EPSK 1e-6f
#define ITS  20

// ---------------- static device scratch (allocation-free) ----------------
__device__ float  g_Xt[(size_t)SMAX*NMAX*DDIM];   // 64MB gathered treated
__device__ float  g_Xc[(size_t)SMAX*NMAX*DDIM];   // 64MB gathered control
__device__ float  g_nrmT[SMAX*NMAX];
__device__ float  g_nrmC[SMAX*NMAX];
__device__ __half g_Km[(size_t)GSZ*CAP];          // 288MB K (fp16), augmented+padded
__device__ float  g_Mm[(size_t)GSZ*CAP];          // 576MB M (fp32), augmented
__device__ float  g_y[GSZ*VLD];
__device__ float  g_z[GSZ*VLD];
__device__ int    g_it[NMAX], g_ic[NMAX];
__device__ int    g_nt, g_nc, g_ld;
__device__ float  g_a0, g_an, g_b0, g_bn;
__device__ float  g_psum[SMAX*1024];
__device__ float  g_pmax[SMAX*1024];
__device__ float  g_sumv[SMAX], g_maxv[SMAX];
__device__ float  g_cpart[SMAX*129];

// ---------------- partition: scan t, index lists + scalars ----------------
__global__ void partition_k(const int* __restrict__ t) {
    __shared__ int cnt[256];
    const int tid = threadIdx.x;
    const int base = tid * 16;
    int c = 0;
    #pragma unroll
    for (int k = 0; k < 16; k++) c += (t[base + k] > 0);
    cnt[tid] = c;
    __syncthreads();
    for (int off = 1; off < 256; off <<= 1) {
        int v = (tid >= off) ? cnt[tid - off] : 0;
        __syncthreads();
        cnt[tid] += v;
        __syncthreads();
    }
    const int nt = cnt[255];
    int tp = cnt[tid] - c;                 // exclusive prefix of treated
    for (int k = 0; k < 16; k++) {
        int idx = base + k;
        if (t[idx] > 0) { g_it[tp] = idx; tp++; }
        else            { g_ic[idx - tp] = idx; }
    }
    if (!tid) {
        int nc = NMAX - nt;
        g_nt = nt; g_nc = nc;
        g_ld = ((nc + 1 + 63) >> 6) << 6;  // 128B-aligned half rows
        float p = (float)nt / (float)NMAX;
        g_a0 = p / (float)nt;       g_an = 1.0f - p;
        g_b0 = (1.0f - p) / (float)nc; g_bn = p;
    }
}

// ---------------- gather rows (one thread per output element) ----------------
__global__ void gather_k(const float* __restrict__ X) {
    size_t idx = (size_t)blockIdx.x * 256 + threadIdx.x;   // over SMAX*NMAX*DDIM
    int d = (int)(idx & 127);
    int r = (int)((idx >> 7) & 4095);
    int s = (int)(idx >> 19);
    if (r < g_nt) g_Xt[idx] = X[(((size_t)g_it[r]) * SMAX + s) * DDIM + d];
    if (r < g_nc) g_Xc[idx] = X[(((size_t)g_ic[r]) * SMAX + s) * DDIM + d];
}

// ---------------- squared row norms (one warp per row) ----------------
__global__ void norms_k() {
    const int gidx = blockIdx.x * 8 + (threadIdx.x >> 5);
    const int lane = threadIdx.x & 31;
    const int s = gidx >> 12, r = gidx & 4095;
    if (r < g_nt) {
        float4 v = *(const float4*)(g_Xt + ((size_t)s * NMAX + r) * DDIM + lane * 4);
        float sq = v.x*v.x + v.y*v.y + v.z*v.z + v.w*v.w;
        #pragma unroll
        for (int o = 16; o; o >>= 1) sq += __shfl_down_sync(~0u, sq, o);
        if (!lane) g_nrmT[s * NMAX + r] = sq;
    }
    if (r < g_nc) {
        float4 v = *(const float4*)(g_Xc + ((size_t)s * NMAX + r) * DDIM + lane * 4);
        float sq = v.x*v.x + v.y*v.y + v.z*v.z + v.w*v.w;
        #pragma unroll
        for (int o = 16; o; o >>= 1) sq += __shfl_down_sync(~0u, sq, o);
        if (!lane) g_nrmC[s * NMAX + r] = sq;
    }
}

// ---------------- GEMM: M = nt + nc - 2 Xt Xc^T, with per-block max/sum partials --------
__global__ __launch_bounds__(256) void gemm_k() {
    const int nt = g_nt, nc = g_nc, ld = g_ld;
    const int by = blockIdx.y, bx = blockIdx.x, gz = blockIdx.z;
    const int s = gz;
    const int tid = threadIdx.x;
    if (by * 128 >= nt || bx * 128 >= nc) {
        if (!tid) { g_psum[s*1024 + by*32 + bx] = 0.f; g_pmax[s*1024 + by*32 + bx] = 0.f; }
        return;
    }
    const float* A = g_Xt + ((size_t)s * NMAX + by * 128) * DDIM;
    const float* B = g_Xc + ((size_t)s * NMAX + bx * 128) * DDIM;
    __shared__ float As[32][132];
    __shared__ float Bs[32][132];
    const int tx = tid & 15, ty = tid >> 4;
    float acc[8][8];
    #pragma unroll
    for (int i = 0; i < 8; i++)
        #pragma unroll
        for (int j = 0; j < 8; j++) acc[i][j] = 0.f;

    for (int k0 = 0; k0 < DDIM; k0 += 32) {
        __syncthreads();
        #pragma unroll
        for (int l = 0; l < 4; l++) {
            int fv = l * 256 + tid, r = fv >> 3, kv = fv & 7;
            float4 va = *(const float4*)(A + (size_t)r * DDIM + k0 + kv * 4);
            As[kv*4+0][r] = va.x; As[kv*4+1][r] = va.y; As[kv*4+2][r] = va.z; As[kv*4+3][r] = va.w;
            float4 vb = *(const float4*)(B + (size_t)r * DDIM + k0 + kv * 4);
            Bs[kv*4+0][r] = vb.x; Bs[kv*4+1][r] = vb.y; Bs[kv*4+2][r] = vb.z; Bs[kv*4+3][r] = vb.w;
        }
        __syncthreads();
        #pragma unroll
        for (int kk = 0; kk < 32; kk++) {
            float av[8], bv[8];
            *(float4*)av       = *(const float4*)&As[kk][ty * 4];
            *(float4*)(av + 4) = *(const float4*)&As[kk][64 + ty * 4];
            *(float4*)bv       = *(const float4*)&Bs[kk][tx * 4];
            *(float4*)(bv + 4) = *(const float4*)&Bs[kk][64 + tx * 4];
            #pragma unroll
            for (int i = 0; i < 8; i++)
                #pragma unroll
                for (int j = 0; j < 8; j++) acc[i][j] = fmaf(av[i], bv[j], acc[i][j]);
        }
    }

    float* Mp = g_Mm + (size_t)gz * CAP;
    float lmax = 0.f, lsum = 0.f;
    #pragma unroll
    for (int ri = 0; ri < 8; ri++) {
        int r = by * 128 + ((ri < 4) ? ty * 4 + ri : 64 + ty * 4 + (ri - 4));
        if (r >= nt) continue;
        float nr = g_nrmT[s * NMAX + r];
        #pragma unroll
        for (int q = 0; q < 2; q++) {
            int cb = bx * 128 + q * 64 + tx * 4;
            float m[4];
            #pragma unroll
            for (int e = 0; e < 4; e++) m[e] = fmaf(-2.f, acc[ri][q*4+e], nr + g_nrmC[s*NMAX + cb + e]);
            if (cb + 3 < nc) {
                *(float4*)(Mp + (size_t)r * ld + cb) = make_float4(m[0], m[1], m[2], m[3]);
                lmax = fmaxf(lmax, fmaxf(fmaxf(m[0], m[1]), fmaxf(m[2], m[3])));
                lsum += (m[0] + m[1]) + (m[2] + m[3]);
            } else {
                #pragma unroll
                for (int e = 0; e < 4; e++) if (cb + e < nc) {
                    Mp[(size_t)r * ld + cb + e] = m[e];
                    lmax = fmaxf(lmax, m[e]); lsum += m[e];
                }
            }
        }
    }
    #pragma unroll
    for (int o = 16; o; o >>= 1) {
        lmax = fmaxf(lmax, __shfl_down_sync(~0u, lmax, o));
        lsum += __shfl_down_sync(~0u, lsum, o);
    }
    __shared__ float rmx[8], rsm[8];
    if (!(tid & 31)) { rmx[tid >> 5] = lmax; rsm[tid >> 5] = lsum; }
    __syncthreads();
    if (!tid) {
        float mx = rmx[0], sm = rsm[0];
        #pragma unroll
        for (int w = 1; w < 8; w++) { mx = fmaxf(mx, rmx[w]); sm += rsm[w]; }
        g_pmax[s*1024 + by*32 + bx] = mx;
        g_psum[s*1024 + by*32 + bx] = sm;
    }
}

// ---------------- deterministic reduce of per-block partials ----------------
__global__ void reduce_k() {
    const int s = blockIdx.x, tid = threadIdx.x;
    __shared__ float ss[256], sm[256];
    float a = 0.f, m = 0.f;
    for (int k = tid; k < 1024; k += 256) { a += g_psum[s*1024 + k]; m = fmaxf(m, g_pmax[s*1024 + k]); }
    ss[tid] = a; sm[tid] = m;
    __syncthreads();
    for (int o = 128; o; o >>= 1) {
        if (tid < o) { ss[tid] += ss[tid + o]; sm[tid] = fmaxf(sm[tid], sm[tid + o]); }
        __syncthreads();
    }
    if (!tid) { g_sumv[s] = ss[0]; g_maxv[s] = sm[0]; }
}

// ---------------- build K = exp(-el*Mt)+eps (fp16), augment M, init z=1 -------
__global__ void kbuild_k() {
    const int nt = g_nt, nc = g_nc, ld = g_ld;
    const int i = blockIdx.x;
    if (i > nt) return;
    const int g = blockIdx.y, s = g, tid = threadIdx.x;
    const float delta = g_maxv[s];
    const float el = ((float)nt * (float)nc) / g_sumv[s];   // lam=1 / mean(M)
    const float Kd = __expf(-el * delta) + EPSK;
    __half* Kp = g_Km + (size_t)g * CAP + (size_t)i * ld;
    float*  Mp = g_Mm + (size_t)g * CAP + (size_t)i * ld;
    if (i < nt) {
        for (int j = tid; j < ld; j += 256) {
            float kv;
            if (j < nc)       kv = __expf(-el * Mp[j]) + EPSK;
            else if (j == nc) { kv = Kd; Mp[j] = delta; }
            else              kv = 0.f;
            Kp[j] = __float2half(kv);
        }
    } else {
        for (int j = tid; j < ld; j += 256) {
            float kv;
            if (j < nc)       { kv = Kd; Mp[j] = delta; }
            else if (j == nc) { kv = 1.0f + EPSK; Mp[j] = 0.f; }
            else              kv = 0.f;
            Kp[j] = __float2half(kv);
        }
    }
    if (!tid) g_z[g * VLD + i] = 1.0f;   // first u = a / 1 = a
}

// ---------------- y = K^T u, u = a / z  (column-parallel) ----------------
__global__ __launch_bounds__(256) void spmvA_k() {
    const int nt = g_nt, nc = g_nc, ld = g_ld;
    const int j0 = blockIdx.x * 128;
    if (j0 > nc) return;
    const int g = blockIdx.y, tid = threadIdx.x;
    __shared__ float us[NMAX + 1];
    __shared__ float red[16 * 128];
    const float a0 = g_a0, an = g_an;
    const float* zp = g_z + g * VLD;
    for (int i = tid; i <= nt; i += 256) us[i] = ((i < nt) ? a0 : an) / zp[i];
    __syncthreads();
    const int cg = tid & 15, ph = tid >> 4;
    const __half* Kp = g_Km + (size_t)g * CAP + j0 + cg * 8;
    float acc[8];
    #pragma unroll
    for (int k = 0; k < 8; k++) acc[k] = 0.f;
    #pragma unroll 4
    for (int i = ph; i <= nt; i += 16) {
        uint4 kv = *(const uint4*)(Kp + (size_t)i * ld);
        float u = us[i];
        const __half2* h = (const __half2*)&kv;
        float2 f;
        f = __half22float2(h[0]); acc[0] = fmaf(f.x, u, acc[0]); acc[1] = fmaf(f.y, u, acc[1]);
        f = __half22float2(h[1]); acc[2] = fmaf(f.x, u, acc[2]); acc[3] = fmaf(f.y, u, acc[3]);
        f = __half22float2(h[2]); acc[4] = fmaf(f.x, u, acc[4]); acc[5] = fmaf(f.y, u, acc[5]);
        f = __half22float2(h[3]); acc[6] = fmaf(f.x, u, acc[6]); acc[7] = fmaf(f.y, u, acc[7]);
    }
    #pragma unroll
    for (int k = 0; k < 8; k++) red[ph * 128 + cg * 8 + k] = acc[k];
    __syncthreads();
    if (tid < 128) {
        float y = 0.f;
        #pragma unroll
        for (int p = 0; p < 16; p++) y += red[p * 128 + tid];
        int j = j0 + tid;
        if (j <= nc) g_y[g * VLD + j] = y;
    }
}

// ---------------- z = K w, w = b / y  (row-parallel, 32 rows/block) ----------
__global__ __launch_bounds__(256) void spmvB_k() {
    const int nt = g_nt, nc = g_nc, ld = g_ld;
    const int bx = blockIdx.x, g = blockIdx.y, tid = threadIdx.x;
    const int i0 = bx * 32;
    if (i0 > nt) return;
    __shared__ __align__(16) float ws[VLD];
    const float b0 = g_b0, bn = g_bn;
    const float* yp = g_y + g * VLD;
    for (int j = tid; j < ld; j += 256) {
        float w = 0.f;
        if (j <= nc) w = ((j < nc) ? b0 : bn) / yp[j];
        ws[j] = w;
    }
    __syncthreads();
    const int lane = tid & 31, wid = tid >> 5;
    for (int rr = 0; rr < 4; rr++) {
        int row = i0 + wid * 4 + rr;
        if (row > nt) break;
        const __half* Kp = g_Km + (size_t)g * CAP + (size_t)row * ld;
        float acc = 0.f;
        #pragma unroll 2
        for (int jb = lane * 8; jb < ld; jb += 256) {
            uint4 kv = *(const uint4*)(Kp + jb);
            float4 w0 = *(const float4*)(ws + jb);
            float4 w1 = *(const float4*)(ws + jb + 4);
            const __half2* h = (const __half2*)&kv;
            float2 f;
            f = __half22float2(h[0]); acc = fmaf(f.x, w0.x, acc); acc = fmaf(f.y, w0.y, acc);
            f = __half22float2(h[1]); acc = fmaf(f.x, w0.z, acc); acc = fmaf(f.y, w0.w, acc);
            f = __half22float2(h[2]); acc = fmaf(f.x, w1.x, acc); acc = fmaf(f.y, w1.y, acc);
            f = __half22float2(h[3]); acc = fmaf(f.x, w1.z, acc); acc = fmaf(f.y, w1.w, acc);
        }
        #pragma unroll
        for (int o = 16; o; o >>= 1) acc += __shfl_down_sync(~0u, acc, o);
        if (!lane) g_z[g * VLD + row] = acc;
    }
}

// ---------------- partial = sum_ij u_i v_j K_ij Mt_ij  ----------------
__global__ __launch_bounds__(256) void contract_k() {
    const int nt = g_nt, nc = g_nc, ld = g_ld;
    const int bx = blockIdx.x, g = blockIdx.y;
    const int s = g, tid = threadIdx.x;
    const int i0 = bx * 32;
    if (i0 > nt) { if (!tid) g_cpart[s * 129 + bx] = 0.f; return; }
    __shared__ __align__(16) float ws[VLD];
    __shared__ float wp[8];
    const float b0 = g_b0, bn = g_bn, a0 = g_a0, an = g_an;
    const float* yp = g_y + g * VLD;
    for (int j = tid; j < ld; j += 256) {
        float w = 0.f;
        if (j <= nc) w = ((j < nc) ? b0 : bn) / yp[j];
        ws[j] = w;
    }
    __syncthreads();
    const int lane = tid & 31, wid = tid >> 5;
    float wsum = 0.f;
    for (int rr = 0; rr < 4; rr++) {
        int row = i0 + wid * 4 + rr;
        if (row > nt) break;
        const __half* Kp = g_Km + (size_t)g * CAP + (size_t)row * ld;
        const float*  Mp = g_Mm + (size_t)g * CAP + (size_t)row * ld;
        float acc = 0.f;
        for (int jb = lane * 8; jb < ld; jb += 256) {
            uint4 kv = *(const uint4*)(Kp + jb);
            float4 m0 = *(const float4*)(Mp + jb);
            float4 m1 = *(const float4*)(Mp + jb + 4);
            float4 w0 = *(const float4*)(ws + jb);
            float4 w1 = *(const float4*)(ws + jb + 4);
            const __half2* h = (const __half2*)&kv;
            float2 f;
            f = __half22float2(h[0]); acc = fmaf(f.x * m0.x, w0.x, acc); acc = fmaf(f.y * m0.y, w0.y, acc);
            f = __half22float2(h[1]); acc = fmaf(f.x * m0.z, w0.z, acc); acc = fmaf(f.y * m0.w, w0.w, acc);
            f = __half22float2(h[2]); acc = fmaf(f.x * m1.x, w1.x, acc); acc = fmaf(f.y * m1.y, w1.y, acc);
            f = __half22float2(h[3]); acc = fmaf(f.x * m1.z, w1.z, acc); acc = fmaf(f.y * m1.w, w1.w, acc);
        }
        #pragma unroll
        for (int o = 16; o; o >>= 1) acc += __shfl_down_sync(~0u, acc, o);
        if (!lane) {
            float u = ((row < nt) ? a0 : an) / g_z[g * VLD + row];
            wsum += u * acc;
        }
    }
    if (!lane) wp[wid] = wsum;
    __syncthreads();
    if (!tid) {
        float t2 = 0.f;
        #pragma unroll
        for (int w = 0; w < 8; w++) t2 += wp[w];
        g_cpart[s * 129 + bx] = t2;
    }
}

// ---------------- final deterministic sum -> d_out ----------------
__global__ void final_k(float* __restrict__ out) {
    __shared__ float ss[256];
    const int tid = threadIdx.x;
    float a = 0.f;
    for (int k = tid; k < SMAX * 129; k += 256) a += g_cpart[k];
    ss[tid] = a;
    __syncthreads();
    for (int o = 128; o; o >>= 1) { if (tid < o) ss[tid] += ss[tid + o]; __syncthreads(); }
    if (!tid) out[0] = 2.0f * ss[0];
}

extern "C" void kernel_launch(void* const* d_in, const int* in_sizes, int n_in,
                              void* d_out, int out_size) {
    (void)in_sizes; (void)n_in; (void)out_size;
    const float* X = (const float*)d_in[0];
    const int*   t = (const int*)d_in[1];

    partition_k<<<1, 256>>>(t);
    gather_k<<<(SMAX * NMAX * DDIM) / 256, 256>>>(X);
    norms_k<<<(SMAX * NMAX) / 8, 256>>>();

    gemm_k<<<dim3(32, 32, SMAX), 256>>>();
    reduce_k<<<SMAX, 256>>>();
    kbuild_k<<<dim3(NMAX + 1, SMAX), 256>>>();
    for (int it = 0; it < ITS; ++it) {
        spmvA_k<<<dim3(33, SMAX), 256>>>();
        spmvB_k<<<dim3(129, SMAX), 256>>>();
    }
    spmvA_k<<<dim3(33, SMAX), 256>>>();   // y for v = b/(K^T u_final)
    contract_k<<<dim3(129, SMAX), 256>>>();
    final_k<<<1, 256>>>((float*)d_out);
}

// round 9
// speedup vs baseline: 1.3149x; 1.2946x over previous
#include <cuda_runtime.h>
#include <cuda_fp16.h>

#define NMAX 4096
#define SMAX 32
#define DDIM 128
#define CAP  4500000u
#define VLD  4224
#define EPSK 1e-6f
#define ITS  20
#define NB   148
#define NTH  1024

// ---------------- static device scratch (allocation-free) ----------------
__device__ float  g_Xt[(size_t)SMAX*NMAX*DDIM];
__device__ float  g_Xc[(size_t)SMAX*NMAX*DDIM];
__device__ float  g_nrmT[SMAX*NMAX];
__device__ float  g_nrmC[SMAX*NMAX];
__device__ __half g_Km[(size_t)SMAX*CAP];          // 288MB K (fp16)
__device__ float  g_Mm[(size_t)SMAX*CAP];          // 576MB M (fp32)
__device__ float  g_y[SMAX*VLD];
__device__ float  g_z[SMAX*VLD];                   // holds u after each B phase
__device__ int    g_it[NMAX], g_ic[NMAX];
__device__ int    g_nt, g_nc, g_ld;
__device__ float  g_a0, g_an, g_b0, g_bn;
__device__ float  g_psum[SMAX*1024];
__device__ float  g_pmax[SMAX*1024];
__device__ float  g_sumv[SMAX], g_maxv[SMAX];
__device__ float  g_cpart[SMAX*129];
__device__ unsigned g_barcnt, g_bargen;

// ---------------- grid-wide barrier (all NB blocks resident) ----------------
__device__ __forceinline__ void grid_sync() {
    __syncthreads();
    if (threadIdx.x == 0) {
        __threadfence();
        unsigned gen = atomicAdd(&g_bargen, 0u);
        if (atomicAdd(&g_barcnt, 1u) == NB - 1) {
            atomicExch(&g_barcnt, 0u);
            __threadfence();
            atomicAdd(&g_bargen, 1u);
        } else {
            while (atomicAdd(&g_bargen, 0u) == gen) {}
        }
        __threadfence();
    }
    __syncthreads();
}

// ---------------- partition: scan t, index lists + scalars ----------------
__global__ void partition_k(const int* __restrict__ t) {
    __shared__ int cnt[256];
    const int tid = threadIdx.x;
    const int base = tid * 16;
    int c = 0;
    #pragma unroll
    for (int k = 0; k < 16; k++) c += (t[base + k] > 0);
    cnt[tid] = c;
    __syncthreads();
    for (int off = 1; off < 256; off <<= 1) {
        int v = (tid >= off) ? cnt[tid - off] : 0;
        __syncthreads();
        cnt[tid] += v;
        __syncthreads();
    }
    const int nt = cnt[255];
    int tp = cnt[tid] - c;
    for (int k = 0; k < 16; k++) {
        int idx = base + k;
        if (t[idx] > 0) { g_it[tp] = idx; tp++; }
        else            { g_ic[idx - tp] = idx; }
    }
    if (!tid) {
        int nc = NMAX - nt;
        g_nt = nt; g_nc = nc;
        g_ld = ((nc + 1 + 63) >> 6) << 6;
        float p = (float)nt / (float)NMAX;
        g_a0 = p / (float)nt;       g_an = 1.0f - p;
        g_b0 = (1.0f - p) / (float)nc; g_bn = p;
    }
}

// ---------------- gather rows ----------------
__global__ void gather_k(const float* __restrict__ X) {
    size_t idx = (size_t)blockIdx.x * 256 + threadIdx.x;
    int d = (int)(idx & 127);
    int r = (int)((idx >> 7) & 4095);
    int s = (int)(idx >> 19);
    if (r < g_nt) g_Xt[idx] = X[(((size_t)g_it[r]) * SMAX + s) * DDIM + d];
    if (r < g_nc) g_Xc[idx] = X[(((size_t)g_ic[r]) * SMAX + s) * DDIM + d];
}

// ---------------- squared row norms ----------------
__global__ void norms_k() {
    const int gidx = blockIdx.x * 8 + (threadIdx.x >> 5);
    const int lane = threadIdx.x & 31;
    const int s = gidx >> 12, r = gidx & 4095;
    if (r < g_nt) {
        float4 v = *(const float4*)(g_Xt + ((size_t)s * NMAX + r) * DDIM + lane * 4);
        float sq = v.x*v.x + v.y*v.y + v.z*v.z + v.w*v.w;
        #pragma unroll
        for (int o = 16; o; o >>= 1) sq += __shfl_down_sync(~0u, sq, o);
        if (!lane) g_nrmT[s * NMAX + r] = sq;
    }
    if (r < g_nc) {
        float4 v = *(const float4*)(g_Xc + ((size_t)s * NMAX + r) * DDIM + lane * 4);
        float sq = v.x*v.x + v.y*v.y + v.z*v.z + v.w*v.w;
        #pragma unroll
        for (int o = 16; o; o >>= 1) sq += __shfl_down_sync(~0u, sq, o);
        if (!lane) g_nrmC[s * NMAX + r] = sq;
    }
}

// ---------------- GEMM: M = nrT + nrC - 2 Xt Xc^T, per-block max/sum ----------
__global__ __launch_bounds__(256) void gemm_k() {
    const int nt = g_nt, nc = g_nc, ld = g_ld;
    const int by = blockIdx.y, bx = blockIdx.x, gz = blockIdx.z;
    const int s = gz;
    const int tid = threadIdx.x;
    if (by * 128 >= nt || bx * 128 >= nc) {
        if (!tid) { g_psum[s*1024 + by*32 + bx] = 0.f; g_pmax[s*1024 + by*32 + bx] = 0.f; }
        return;
    }
    const float* A = g_Xt + ((size_t)s * NMAX + by * 128) * DDIM;
    const float* B = g_Xc + ((size_t)s * NMAX + bx * 128) * DDIM;
    __shared__ float As[32][132];
    __shared__ float Bs[32][132];
    const int tx = tid & 15, ty = tid >> 4;
    float acc[8][8];
    #pragma unroll
    for (int i = 0; i < 8; i++)
        #pragma unroll
        for (int j = 0; j < 8; j++) acc[i][j] = 0.f;

    for (int k0 = 0; k0 < DDIM; k0 += 32) {
        __syncthreads();
        #pragma unroll
        for (int l = 0; l < 4; l++) {
            int fv = l * 256 + tid, r = fv >> 3, kv = fv & 7;
            float4 va = *(const float4*)(A + (size_t)r * DDIM + k0 + kv * 4);
            As[kv*4+0][r] = va.x; As[kv*4+1][r] = va.y; As[kv*4+2][r] = va.z; As[kv*4+3][r] = va.w;
            float4 vb = *(const float4*)(B + (size_t)r * DDIM + k0 + kv * 4);
            Bs[kv*4+0][r] = vb.x; Bs[kv*4+1][r] = vb.y; Bs[kv*4+2][r] = vb.z; Bs[kv*4+3][r] = vb.w;
        }
        __syncthreads();
        #pragma unroll
        for (int kk = 0; kk < 32; kk++) {
            float av[8], bv[8];
            *(float4*)av       = *(const float4*)&As[kk][ty * 4];
            *(float4*)(av + 4) = *(const float4*)&As[kk][64 + ty * 4];
            *(float4*)bv       = *(const float4*)&Bs[kk][tx * 4];
            *(float4*)(bv + 4) = *(const float4*)&Bs[kk][64 + tx * 4];
            #pragma unroll
            for (int i = 0; i < 8; i++)
                #pragma unroll
                for (int j = 0; j < 8; j++) acc[i][j] = fmaf(av[i], bv[j], acc[i][j]);
        }
    }

    float* Mp = g_Mm + (size_t)gz * CAP;
    float lmax = 0.f, lsum = 0.f;
    #pragma unroll
    for (int ri = 0; ri < 8; ri++) {
        int r = by * 128 + ((ri < 4) ? ty * 4 + ri : 64 + ty * 4 + (ri - 4));
        if (r >= nt) continue;
        float nr = g_nrmT[s * NMAX + r];
        #pragma unroll
        for (int q = 0; q < 2; q++) {
            int cb = bx * 128 + q * 64 + tx * 4;
            float m[4];
            #pragma unroll
            for (int e = 0; e < 4; e++) m[e] = fmaf(-2.f, acc[ri][q*4+e], nr + g_nrmC[s*NMAX + cb + e]);
            if (cb + 3 < nc) {
                *(float4*)(Mp + (size_t)r * ld + cb) = make_float4(m[0], m[1], m[2], m[3]);
                lmax = fmaxf(lmax, fmaxf(fmaxf(m[0], m[1]), fmaxf(m[2], m[3])));
                lsum += (m[0] + m[1]) + (m[2] + m[3]);
            } else {
                #pragma unroll
                for (int e = 0; e < 4; e++) if (cb + e < nc) {
                    Mp[(size_t)r * ld + cb + e] = m[e];
                    lmax = fmaxf(lmax, m[e]); lsum += m[e];
                }
            }
        }
    }
    #pragma unroll
    for (int o = 16; o; o >>= 1) {
        lmax = fmaxf(lmax, __shfl_down_sync(~0u, lmax, o));
        lsum += __shfl_down_sync(~0u, lsum, o);
    }
    __shared__ float rmx[8], rsm[8];
    if (!(tid & 31)) { rmx[tid >> 5] = lmax; rsm[tid >> 5] = lsum; }
    __syncthreads();
    if (!tid) {
        float mx = rmx[0], sm = rsm[0];
        #pragma unroll
        for (int w = 1; w < 8; w++) { mx = fmaxf(mx, rmx[w]); sm += rsm[w]; }
        g_pmax[s*1024 + by*32 + bx] = mx;
        g_psum[s*1024 + by*32 + bx] = sm;
    }
}

// ---------------- deterministic reduce of per-block partials ----------------
__global__ void reduce_k() {
    const int s = blockIdx.x, tid = threadIdx.x;
    __shared__ float ss[256], sm[256];
    float a = 0.f, m = 0.f;
    for (int k = tid; k < 1024; k += 256) { a += g_psum[s*1024 + k]; m = fmaxf(m, g_pmax[s*1024 + k]); }
    ss[tid] = a; sm[tid] = m;
    __syncthreads();
    for (int o = 128; o; o >>= 1) {
        if (tid < o) { ss[tid] += ss[tid + o]; sm[tid] = fmaxf(sm[tid], sm[tid + o]); }
        __syncthreads();
    }
    if (!tid) { g_sumv[s] = ss[0]; g_maxv[s] = sm[0]; }
}

// -------- build K = exp(-el*Mt)+eps (fp16), augment M, seed u0 = a ----------
__global__ void kbuild_k() {
    const int nt = g_nt, nc = g_nc, ld = g_ld;
    const int i = blockIdx.x;
    if (i > nt) return;
    const int g = blockIdx.y, s = g, tid = threadIdx.x;
    const float delta = g_maxv[s];
    const float el = ((float)nt * (float)nc) / g_sumv[s];
    const float Kd = __expf(-el * delta) + EPSK;
    __half* Kp = g_Km + (size_t)g * CAP + (size_t)i * ld;
    float*  Mp = g_Mm + (size_t)g * CAP + (size_t)i * ld;
    if (i < nt) {
        for (int j = tid; j < ld; j += 256) {
            float kv;
            if (j < nc)       kv = __expf(-el * Mp[j]) + EPSK;
            else if (j == nc) { kv = Kd; Mp[j] = delta; }
            else              kv = 0.f;
            Kp[j] = __float2half(kv);
        }
    } else {
        for (int j = tid; j < ld; j += 256) {
            float kv;
            if (j < nc)       { kv = Kd; Mp[j] = delta; }
            else if (j == nc) { kv = 1.0f + EPSK; Mp[j] = 0.f; }
            else              kv = 0.f;
            Kp[j] = __float2half(kv);
        }
    }
    if (!tid) g_z[g * VLD + i] = (i < nt) ? g_a0 : g_an;   // u0 = a (z0 = 1)
}

// ------------- persistent Sinkhorn: 20x (A,B) + final A, one kernel ----------
__global__ __launch_bounds__(NTH, 1) void sinkhorn_k() {
    const int nt = g_nt, nc = g_nc, ld = g_ld;
    const int bid = blockIdx.x, tid = threadIdx.x;
    __shared__ __align__(16) float us[VLD];        // u (A) / w (B)
    __shared__ float red[32 * 128];
    const float a0 = g_a0, an = g_an, b0 = g_b0, bn = g_bn;
    const int nj = (nc + 1 + 127) >> 7;
    const int ni = (nt + 1 + 127) >> 7;

    for (int half = 0; half < 2 * ITS + 1; ++half) {
        if ((half & 1) == 0) {
            // ---- A: y_j = sum_i K_ij u_i ----
            for (int tile = bid; tile < SMAX * nj; tile += NB) {
                const int g = tile / nj;
                const int j0 = (tile - g * nj) << 7;
                const float* up = g_z + g * VLD;
                __syncthreads();
                for (int i = tid; i <= nt; i += NTH) us[i] = up[i];
                __syncthreads();
                const int cg = tid & 31, ph = tid >> 5;
                const __half* Kp = g_Km + (size_t)g * CAP + j0 + cg * 4;
                float acc0 = 0.f, acc1 = 0.f, acc2 = 0.f, acc3 = 0.f;
                #pragma unroll 8
                for (int i = ph; i <= nt; i += 32) {
                    uint2 kv = *(const uint2*)(Kp + (size_t)i * ld);
                    float u = us[i];
                    float2 f0 = __half22float2(*(__half2*)&kv.x);
                    float2 f1 = __half22float2(*(__half2*)&kv.y);
                    acc0 = fmaf(f0.x, u, acc0); acc1 = fmaf(f0.y, u, acc1);
                    acc2 = fmaf(f1.x, u, acc2); acc3 = fmaf(f1.y, u, acc3);
                }
                red[ph * 128 + cg * 4 + 0] = acc0;
                red[ph * 128 + cg * 4 + 1] = acc1;
                red[ph * 128 + cg * 4 + 2] = acc2;
                red[ph * 128 + cg * 4 + 3] = acc3;
                __syncthreads();
                if (tid < 128) {
                    float y = 0.f;
                    #pragma unroll
                    for (int p = 0; p < 32; p++) y += red[p * 128 + tid];
                    int j = j0 + tid;
                    if (j <= nc) g_y[g * VLD + j] = y;
                }
            }
        } else {
            // ---- B: z_i = sum_j K_ij b_j/y_j ; u_i = a_i/z_i ----
            for (int tile = bid; tile < SMAX * ni; tile += NB) {
                const int g = tile / ni;
                const int i0 = (tile - g * ni) << 7;
                const float* yp = g_y + g * VLD;
                __syncthreads();
                for (int j = tid; j < ld; j += NTH) {
                    float w = 0.f;
                    if (j <= nc) w = ((j < nc) ? b0 : bn) / yp[j];
                    us[j] = w;
                }
                __syncthreads();
                const int lane = tid & 31, wid = tid >> 5;
                for (int rr = 0; rr < 4; rr++) {
                    int row = i0 + wid * 4 + rr;
                    if (row > nt) break;
                    const __half* Kp = g_Km + (size_t)g * CAP + (size_t)row * ld;
                    float acc = 0.f;
                    #pragma unroll 2
                    for (int jb = lane * 8; jb < ld; jb += 256) {
                        uint4 kv = *(const uint4*)(Kp + jb);
                        float4 w0 = *(const float4*)(us + jb);
                        float4 w1 = *(const float4*)(us + jb + 4);
                        const __half2* h = (const __half2*)&kv;
                        float2 f;
                        f = __half22float2(h[0]); acc = fmaf(f.x, w0.x, acc); acc = fmaf(f.y, w0.y, acc);
                        f = __half22float2(h[1]); acc = fmaf(f.x, w0.z, acc); acc = fmaf(f.y, w0.w, acc);
                        f = __half22float2(h[2]); acc = fmaf(f.x, w1.x, acc); acc = fmaf(f.y, w1.y, acc);
                        f = __half22float2(h[3]); acc = fmaf(f.x, w1.z, acc); acc = fmaf(f.y, w1.w, acc);
                    }
                    #pragma unroll
                    for (int o = 16; o; o >>= 1) acc += __shfl_down_sync(~0u, acc, o);
                    if (!lane) g_z[g * VLD + row] = ((row < nt) ? a0 : an) / acc;
                }
            }
        }
        grid_sync();
    }
}

// ---------------- partial = sum_ij u_i v_j K_ij Mt_ij ----------------
__global__ __launch_bounds__(256) void contract_k() {
    const int nt = g_nt, nc = g_nc, ld = g_ld;
    const int bx = blockIdx.x, g = blockIdx.y;
    const int s = g, tid = threadIdx.x;
    const int i0 = bx * 32;
    if (i0 > nt) { if (!tid) g_cpart[s * 129 + bx] = 0.f; return; }
    __shared__ __align__(16) float ws[VLD];
    __shared__ float wp[8];
    const float b0 = g_b0, bn = g_bn;
    const float* yp = g_y + g * VLD;
    for (int j = tid; j < ld; j += 256) {
        float w = 0.f;
        if (j <= nc) w = ((j < nc) ? b0 : bn) / yp[j];
        ws[j] = w;
    }
    __syncthreads();
    const int lane = tid & 31, wid = tid >> 5;
    float wsum = 0.f;
    for (int rr = 0; rr < 4; rr++) {
        int row = i0 + wid * 4 + rr;
        if (row > nt) break;
        const __half* Kp = g_Km + (size_t)g * CAP + (size_t)row * ld;
        const float*  Mp = g_Mm + (size_t)g * CAP + (size_t)row * ld;
        float acc = 0.f;
        for (int jb = lane * 8; jb < ld; jb += 256) {
            uint4 kv = *(const uint4*)(Kp + jb);
            float4 m0 = *(const float4*)(Mp + jb);
            float4 m1 = *(const float4*)(Mp + jb + 4);
            float4 w0 = *(const float4*)(ws + jb);
            float4 w1 = *(const float4*)(ws + jb + 4);
            const __half2* h = (const __half2*)&kv;
            float2 f;
            f = __half22float2(h[0]); acc = fmaf(f.x * m0.x, w0.x, acc); acc = fmaf(f.y * m0.y, w0.y, acc);
            f = __half22float2(h[1]); acc = fmaf(f.x * m0.z, w0.z, acc); acc = fmaf(f.y * m0.w, w0.w, acc);
            f = __half22float2(h[2]); acc = fmaf(f.x * m1.x, w1.x, acc); acc = fmaf(f.y * m1.y, w1.y, acc);
            f = __half22float2(h[3]); acc = fmaf(f.x * m1.z, w1.z, acc); acc = fmaf(f.y * m1.w, w1.w, acc);
        }
        #pragma unroll
        for (int o = 16; o; o >>= 1) acc += __shfl_down_sync(~0u, acc, o);
        if (!lane) wsum += g_z[g * VLD + row] * acc;    // g_z holds u
    }
    if (!lane) wp[wid] = wsum;
    __syncthreads();
    if (!tid) {
        float t2 = 0.f;
        #pragma unroll
        for (int w = 0; w < 8; w++) t2 += wp[w];
        g_cpart[s * 129 + bx] = t2;
    }
}

// ---------------- final deterministic sum -> d_out ----------------
__global__ void final_k(float* __restrict__ out) {
    __shared__ float ss[256];
    const int tid = threadIdx.x;
    float a = 0.f;
    for (int k = tid; k < SMAX * 129; k += 256) a += g_cpart[k];
    ss[tid] = a;
    __syncthreads();
    for (int o = 128; o; o >>= 1) { if (tid < o) ss[tid] += ss[tid + o]; __syncthreads(); }
    if (!tid) out[0] = 2.0f * ss[0];
}

extern "C" void kernel_launch(void* const* d_in, const int* in_sizes, int n_in,
                              void* d_out, int out_size) {
    (void)in_sizes; (void)n_in; (void)out_size;
    const float* X = (const float*)d_in[0];
    const int*   t = (const int*)d_in[1];

    partition_k<<<1, 256>>>(t);
    gather_k<<<(SMAX * NMAX * DDIM) / 256, 256>>>(X);
    norms_k<<<(SMAX * NMAX) / 8, 256>>>();

    gemm_k<<<dim3(32, 32, SMAX), 256>>>();
    reduce_k<<<SMAX, 256>>>();
    kbuild_k<<<dim3(NMAX + 1, SMAX), 256>>>();
    sinkhorn_k<<<NB, NTH>>>();
    contract_k<<<dim3(129, SMAX), 256>>>();
    final_k<<<1, 256>>>((float*)d_out);
}

// round 14
// speedup vs baseline: 1.5035x; 1.1434x over previous
#include <cuda_runtime.h>
#include <cuda_fp16.h>

#define NMAX 4096
#define SMAX 32
#define DDIM 128
#define CAP  4500000u
#define VLD  4224
#define EPSK 1e-6f
#define ITS  20
#define NB   148
#define NTH  1024

// ---------------- static device scratch (allocation-free) ----------------
__device__ float  g_Xt[(size_t)SMAX*NMAX*DDIM];
__device__ float  g_Xc[(size_t)SMAX*NMAX*DDIM];
__device__ float  g_nrmT[SMAX*NMAX];
__device__ float  g_nrmC[SMAX*NMAX];
__device__ __half g_Km[(size_t)SMAX*CAP];          // 288MB K (fp16)
__device__ __half g_Mh[(size_t)SMAX*CAP];          // 288MB M (fp16)
__device__ float  g_y[SMAX*VLD];
__device__ float  g_z[SMAX*VLD];                   // holds u after each B phase
__device__ int    g_it[NMAX], g_ic[NMAX];
__device__ int    g_nt, g_nc, g_ld;
__device__ float  g_a0, g_an, g_b0, g_bn;
__device__ float  g_psum[SMAX*1024];
__device__ float  g_pmax[SMAX*1024];
__device__ float  g_sumv[SMAX], g_maxv[SMAX];
__device__ float  g_cpart[SMAX*129];
__device__ unsigned g_barcnt, g_bargen;

// ---------------- grid-wide barrier (all NB blocks resident) ----------------
__device__ __forceinline__ void grid_sync() {
    __syncthreads();
    if (threadIdx.x == 0) {
        __threadfence();
        unsigned gen = atomicAdd(&g_bargen, 0u);
        if (atomicAdd(&g_barcnt, 1u) == NB - 1) {
            atomicExch(&g_barcnt, 0u);
            __threadfence();
            atomicAdd(&g_bargen, 1u);
        } else {
            while (atomicAdd(&g_bargen, 0u) == gen) {}
        }
        __threadfence();
    }
    __syncthreads();
}

__device__ __forceinline__ unsigned f2tf32(float x) {
    unsigned u;
    asm("cvt.rna.tf32.f32 %0, %1;" : "=r"(u) : "f"(x));
    return u;
}

// ---------------- partition: scan t, index lists + scalars ----------------
__global__ void partition_k(const int* __restrict__ t) {
    __shared__ int cnt[256];
    const int tid = threadIdx.x;
    const int base = tid * 16;
    int c = 0;
    #pragma unroll
    for (int k = 0; k < 16; k++) c += (t[base + k] > 0);
    cnt[tid] = c;
    __syncthreads();
    for (int off = 1; off < 256; off <<= 1) {
        int v = (tid >= off) ? cnt[tid - off] : 0;
        __syncthreads();
        cnt[tid] += v;
        __syncthreads();
    }
    const int nt = cnt[255];
    int tp = cnt[tid] - c;
    for (int k = 0; k < 16; k++) {
        int idx = base + k;
        if (t[idx] > 0) { g_it[tp] = idx; tp++; }
        else            { g_ic[idx - tp] = idx; }
    }
    if (!tid) {
        int nc = NMAX - nt;
        g_nt = nt; g_nc = nc;
        g_ld = ((nc + 1 + 63) >> 6) << 6;
        float p = (float)nt / (float)NMAX;
        g_a0 = p / (float)nt;       g_an = 1.0f - p;
        g_b0 = (1.0f - p) / (float)nc; g_bn = p;
    }
}

// ---------------- gather rows ----------------
__global__ void gather_k(const float* __restrict__ X) {
    size_t idx = (size_t)blockIdx.x * 256 + threadIdx.x;
    int d = (int)(idx & 127);
    int r = (int)((idx >> 7) & 4095);
    int s = (int)(idx >> 19);
    if (r < g_nt) g_Xt[idx] = X[(((size_t)g_it[r]) * SMAX + s) * DDIM + d];
    if (r < g_nc) g_Xc[idx] = X[(((size_t)g_ic[r]) * SMAX + s) * DDIM + d];
}

// ---------------- squared row norms ----------------
__global__ void norms_k() {
    const int gidx = blockIdx.x * 8 + (threadIdx.x >> 5);
    const int lane = threadIdx.x & 31;
    const int s = gidx >> 12, r = gidx & 4095;
    if (r < g_nt) {
        float4 v = *(const float4*)(g_Xt + ((size_t)s * NMAX + r) * DDIM + lane * 4);
        float sq = v.x*v.x + v.y*v.y + v.z*v.z + v.w*v.w;
        #pragma unroll
        for (int o = 16; o; o >>= 1) sq += __shfl_down_sync(~0u, sq, o);
        if (!lane) g_nrmT[s * NMAX + r] = sq;
    }
    if (r < g_nc) {
        float4 v = *(const float4*)(g_Xc + ((size_t)s * NMAX + r) * DDIM + lane * 4);
        float sq = v.x*v.x + v.y*v.y + v.z*v.z + v.w*v.w;
        #pragma unroll
        for (int o = 16; o; o >>= 1) sq += __shfl_down_sync(~0u, sq, o);
        if (!lane) g_nrmC[s * NMAX + r] = sq;
    }
}

// ------- TF32 tensor-core GEMM: M = nrT + nrC - 2 Xt Xc^T (fp16 out) --------
__global__ __launch_bounds__(256) void gemm_k() {
    const int nt = g_nt, nc = g_nc, ld = g_ld;
    const int by = blockIdx.y, bx = blockIdx.x, gz = blockIdx.z;
    const int s = gz;
    const int tid = threadIdx.x;
    if (by * 128 >= nt || bx * 128 >= nc) {
        if (!tid) { g_psum[s*1024 + by*32 + bx] = 0.f; g_pmax[s*1024 + by*32 + bx] = 0.f; }
        return;
    }
    const float* A = g_Xt + ((size_t)s * NMAX + by * 128) * DDIM;
    const float* B = g_Xc + ((size_t)s * NMAX + bx * 128) * DDIM;
    __shared__ unsigned As[128][36];
    __shared__ unsigned Bs[128][36];
    const int warp = tid >> 5, lane = tid & 31;
    const int wm = (warp >> 2) * 64, wn = (warp & 3) * 32;
    const int qr = lane >> 2, qc = lane & 3;

    float c[4][4][4];
    #pragma unroll
    for (int mt = 0; mt < 4; mt++)
        #pragma unroll
        for (int nn = 0; nn < 4; nn++)
            #pragma unroll
            for (int e = 0; e < 4; e++) c[mt][nn][e] = 0.f;

    for (int k0 = 0; k0 < DDIM; k0 += 32) {
        __syncthreads();
        #pragma unroll
        for (int l = 0; l < 4; l++) {
            int idx = l * 256 + tid;
            int row = idx >> 3, kq = idx & 7;
            float4 va = *(const float4*)(A + (size_t)row * DDIM + k0 + kq * 4);
            uint4 ua = make_uint4(f2tf32(va.x), f2tf32(va.y), f2tf32(va.z), f2tf32(va.w));
            *(uint4*)&As[row][kq * 4] = ua;
            float4 vb = *(const float4*)(B + (size_t)row * DDIM + k0 + kq * 4);
            uint4 ub = make_uint4(f2tf32(vb.x), f2tf32(vb.y), f2tf32(vb.z), f2tf32(vb.w));
            *(uint4*)&Bs[row][kq * 4] = ub;
        }
        __syncthreads();
        #pragma unroll
        for (int ks = 0; ks < 4; ks++) {
            const int kb = ks * 8 + qc;
            unsigned af[4][4], bf[4][2];
            #pragma unroll
            for (int mt = 0; mt < 4; mt++) {
                int row = wm + mt * 16 + qr;
                af[mt][0] = As[row][kb];
                af[mt][1] = As[row + 8][kb];
                af[mt][2] = As[row][kb + 4];
                af[mt][3] = As[row + 8][kb + 4];
            }
            #pragma unroll
            for (int nn = 0; nn < 4; nn++) {
                int col = wn + nn * 8 + qr;
                bf[nn][0] = Bs[col][kb];
                bf[nn][1] = Bs[col][kb + 4];
            }
            #pragma unroll
            for (int mt = 0; mt < 4; mt++)
                #pragma unroll
                for (int nn = 0; nn < 4; nn++) {
                    asm volatile(
                        "mma.sync.aligned.m16n8k8.row.col.f32.tf32.tf32.f32 "
                        "{%0,%1,%2,%3}, {%4,%5,%6,%7}, {%8,%9}, {%0,%1,%2,%3};\n"
                        : "+f"(c[mt][nn][0]), "+f"(c[mt][nn][1]),
                          "+f"(c[mt][nn][2]), "+f"(c[mt][nn][3])
                        : "r"(af[mt][0]), "r"(af[mt][1]), "r"(af[mt][2]), "r"(af[mt][3]),
                          "r"(bf[nn][0]), "r"(bf[nn][1]));
                }
        }
    }

    // epilogue: M = nrT + nrC - 2*dot, store fp16, reduce max/sum
    __half* Mp = g_Mh + (size_t)gz * CAP;
    float lmax = 0.f, lsum = 0.f;
    #pragma unroll
    for (int mt = 0; mt < 4; mt++) {
        float nrh[2];
        #pragma unroll
        for (int h = 0; h < 2; h++) {
            int gr = by * 128 + wm + mt * 16 + qr + h * 8;
            nrh[h] = (gr < nt) ? g_nrmT[s * NMAX + gr] : 0.f;
        }
        #pragma unroll
        for (int nn = 0; nn < 4; nn++) {
            int gc = bx * 128 + wn + nn * 8 + 2 * qc;
            float nc0 = (gc     < nc) ? g_nrmC[s * NMAX + gc]     : 0.f;
            float nc1 = (gc + 1 < nc) ? g_nrmC[s * NMAX + gc + 1] : 0.f;
            #pragma unroll
            for (int h = 0; h < 2; h++) {
                int gr = by * 128 + wm + mt * 16 + qr + h * 8;
                if (gr >= nt) continue;
                float m0 = fmaf(-2.f, c[mt][nn][h * 2 + 0], nrh[h] + nc0);
                float m1 = fmaf(-2.f, c[mt][nn][h * 2 + 1], nrh[h] + nc1);
                if (gc + 1 < nc) {
                    *(__half2*)(Mp + (size_t)gr * ld + gc) = __floats2half2_rn(m0, m1);
                    lmax = fmaxf(lmax, fmaxf(m0, m1));
                    lsum += m0 + m1;
                } else if (gc < nc) {
                    Mp[(size_t)gr * ld + gc] = __float2half(m0);
                    lmax = fmaxf(lmax, m0);
                    lsum += m0;
                }
            }
        }
    }
    #pragma unroll
    for (int o = 16; o; o >>= 1) {
        lmax = fmaxf(lmax, __shfl_down_sync(~0u, lmax, o));
        lsum += __shfl_down_sync(~0u, lsum, o);
    }
    __shared__ float rmx[8], rsm[8];
    if (!lane) { rmx[warp] = lmax; rsm[warp] = lsum; }
    __syncthreads();
    if (!tid) {
        float mx = rmx[0], sm = rsm[0];
        #pragma unroll
        for (int w = 1; w < 8; w++) { mx = fmaxf(mx, rmx[w]); sm += rsm[w]; }
        g_pmax[s*1024 + by*32 + bx] = mx;
        g_psum[s*1024 + by*32 + bx] = sm;
    }
}

// ---------------- deterministic reduce of per-block partials ----------------
__global__ void reduce_k() {
    const int s = blockIdx.x, tid = threadIdx.x;
    __shared__ float ss[256], sm[256];
    float a = 0.f, m = 0.f;
    for (int k = tid; k < 1024; k += 256) { a += g_psum[s*1024 + k]; m = fmaxf(m, g_pmax[s*1024 + k]); }
    ss[tid] = a; sm[tid] = m;
    __syncthreads();
    for (int o = 128; o; o >>= 1) {
        if (tid < o) { ss[tid] += ss[tid + o]; sm[tid] = fmaxf(sm[tid], sm[tid + o]); }
        __syncthreads();
    }
    if (!tid) { g_sumv[s] = ss[0]; g_maxv[s] = sm[0]; }
}

// -------- build K = exp(-el*Mt)+eps (fp16), augment M, seed u0 = a ----------
__global__ void kbuild_k() {
    const int nt = g_nt, nc = g_nc, ld = g_ld;
    const int i = blockIdx.x;
    if (i > nt) return;
    const int g = blockIdx.y, s = g, tid = threadIdx.x;
    const float delta = g_maxv[s];
    const float el = ((float)nt * (float)nc) / g_sumv[s];
    const float Kd = __expf(-el * delta) + EPSK;
    __half* Kp = g_Km + (size_t)g * CAP + (size_t)i * ld;
    __half* Mp = g_Mh + (size_t)g * CAP + (size_t)i * ld;
    if (i < nt) {
        for (int j = tid; j < ld; j += 256) {
            float kv;
            if (j < nc)       kv = __expf(-el * __half2float(Mp[j])) + EPSK;
            else if (j == nc) { kv = Kd; Mp[j] = __float2half(delta); }
            else              kv = 0.f;
            Kp[j] = __float2half(kv);
        }
    } else {
        for (int j = tid; j < ld; j += 256) {
            float kv;
            if (j < nc)       { kv = Kd; Mp[j] = __float2half(delta); }
            else if (j == nc) { kv = 1.0f + EPSK; Mp[j] = __float2half(0.f); }
            else              kv = 0.f;
            Kp[j] = __float2half(kv);
        }
    }
    if (!tid) g_z[g * VLD + i] = (i < nt) ? g_a0 : g_an;   // u0 = a (z0 = 1)
}

// ------------- persistent Sinkhorn: 20x (A,B) + final A, one kernel ----------
__global__ __launch_bounds__(NTH, 1) void sinkhorn_k() {
    const int nt = g_nt, nc = g_nc, ld = g_ld;
    const int bid = blockIdx.x, tid = threadIdx.x;
    __shared__ __align__(16) float us[VLD];        // u (A) / w (B)
    __shared__ float red[32 * 128];
    const float a0 = g_a0, an = g_an, b0 = g_b0, bn = g_bn;
    const int nj = (nc + 1 + 127) >> 7;
    const int ni = (nt + 1 + 127) >> 7;

    for (int half = 0; half < 2 * ITS + 1; ++half) {
        if ((half & 1) == 0) {
            // ---- A: y_j = sum_i K_ij u_i ----
            for (int tile = bid; tile < SMAX * nj; tile += NB) {
                const int g = tile / nj;
                const int j0 = (tile - g * nj) << 7;
                const float* up = g_z + g * VLD;
                __syncthreads();
                for (int i = tid; i <= nt; i += NTH) us[i] = up[i];
                __syncthreads();
                const int cg = tid & 31, ph = tid >> 5;
                const __half* Kp = g_Km + (size_t)g * CAP + j0 + cg * 4;
                float acc0 = 0.f, acc1 = 0.f, acc2 = 0.f, acc3 = 0.f;
                #pragma unroll 8
                for (int i = ph; i <= nt; i += 32) {
                    uint2 kv = *(const uint2*)(Kp + (size_t)i * ld);
                    float u = us[i];
                    float2 f0 = __half22float2(*(__half2*)&kv.x);
                    float2 f1 = __half22float2(*(__half2*)&kv.y);
                    acc0 = fmaf(f0.x, u, acc0); acc1 = fmaf(f0.y, u, acc1);
                    acc2 = fmaf(f1.x, u, acc2); acc3 = fmaf(f1.y, u, acc3);
                }
                red[ph * 128 + cg * 4 + 0] = acc0;
                red[ph * 128 + cg * 4 + 1] = acc1;
                red[ph * 128 + cg * 4 + 2] = acc2;
                red[ph * 128 + cg * 4 + 3] = acc3;
                __syncthreads();
                if (tid < 128) {
                    float y = 0.f;
                    #pragma unroll
                    for (int p = 0; p < 32; p++) y += red[p * 128 + tid];
                    int j = j0 + tid;
                    if (j <= nc) g_y[g * VLD + j] = y;
                }
            }
        } else {
            // ---- B: z_i = sum_j K_ij b_j/y_j ; u_i = a_i/z_i ----
            for (int tile = bid; tile < SMAX * ni; tile += NB) {
                const int g = tile / ni;
                const int i0 = (tile - g * ni) << 7;
                const float* yp = g_y + g * VLD;
                __syncthreads();
                for (int j = tid; j < ld; j += NTH) {
                    float w = 0.f;
                    if (j <= nc) w = ((j < nc) ? b0 : bn) / yp[j];
                    us[j] = w;
                }
                __syncthreads();
                const int lane = tid & 31, wid = tid >> 5;
                for (int rr = 0; rr < 4; rr++) {
                    int row = i0 + wid * 4 + rr;
                    if (row > nt) break;
                    const __half* Kp = g_Km + (size_t)g * CAP + (size_t)row * ld;
                    float acc = 0.f;
                    #pragma unroll 2
                    for (int jb = lane * 8; jb < ld; jb += 256) {
                        uint4 kv = *(const uint4*)(Kp + jb);
                        float4 w0 = *(const float4*)(us + jb);
                        float4 w1 = *(const float4*)(us + jb + 4);
                        const __half2* h = (const __half2*)&kv;
                        float2 f;
                        f = __half22float2(h[0]); acc = fmaf(f.x, w0.x, acc); acc = fmaf(f.y, w0.y, acc);
                        f = __half22float2(h[1]); acc = fmaf(f.x, w0.z, acc); acc = fmaf(f.y, w0.w, acc);
                        f = __half22float2(h[2]); acc = fmaf(f.x, w1.x, acc); acc = fmaf(f.y, w1.y, acc);
                        f = __half22float2(h[3]); acc = fmaf(f.x, w1.z, acc); acc = fmaf(f.y, w1.w, acc);
                    }
                    #pragma unroll
                    for (int o = 16; o; o >>= 1) acc += __shfl_down_sync(~0u, acc, o);
                    if (!lane) g_z[g * VLD + row] = ((row < nt) ? a0 : an) / acc;
                }
            }
        }
        grid_sync();
    }
}

// ---------------- partial = sum_ij u_i v_j K_ij Mt_ij ----------------
__global__ __launch_bounds__(256) void contract_k() {
    const int nt = g_nt, nc = g_nc, ld = g_ld;
    const int bx = blockIdx.x, g = blockIdx.y;
    const int s = g, tid = threadIdx.x;
    const int i0 = bx * 32;
    if (i0 > nt) { if (!tid) g_cpart[s * 129 + bx] = 0.f; return; }
    __shared__ __align__(16) float ws[VLD];
    __shared__ float wp[8];
    const float b0 = g_b0, bn = g_bn;
    const float* yp = g_y + g * VLD;
    for (int j = tid; j < ld; j += 256) {
        float w = 0.f;
        if (j <= nc) w = ((j < nc) ? b0 : bn) / yp[j];
        ws[j] = w;
    }
    __syncthreads();
    const int lane = tid & 31, wid = tid >> 5;
    float wsum = 0.f;
    for (int rr = 0; rr < 4; rr++) {
        int row = i0 + wid * 4 + rr;
        if (row > nt) break;
        const __half* Kp = g_Km + (size_t)g * CAP + (size_t)row * ld;
        const __half* Mp = g_Mh + (size_t)g * CAP + (size_t)row * ld;
        float acc = 0.f;
        for (int jb = lane * 8; jb < ld; jb += 256) {
            uint4 kv = *(const uint4*)(Kp + jb);
            uint4 mv = *(const uint4*)(Mp + jb);
            float4 w0 = *(const float4*)(ws + jb);
            float4 w1 = *(const float4*)(ws + jb + 4);
            const __half2* h = (const __half2*)&kv;
            const __half2* mm = (const __half2*)&mv;
            float2 f, m2;
            f = __half22float2(h[0]); m2 = __half22float2(mm[0]);
            acc = fmaf(f.x * m2.x, w0.x, acc); acc = fmaf(f.y * m2.y, w0.y, acc);
            f = __half22float2(h[1]); m2 = __half22float2(mm[1]);
            acc = fmaf(f.x * m2.x, w0.z, acc); acc = fmaf(f.y * m2.y, w0.w, acc);
            f = __half22float2(h[2]); m2 = __half22float2(mm[2]);
            acc = fmaf(f.x * m2.x, w1.x, acc); acc = fmaf(f.y * m2.y, w1.y, acc);
            f = __half22float2(h[3]); m2 = __half22float2(mm[3]);
            acc = fmaf(f.x * m2.x, w1.z, acc); acc = fmaf(f.y * m2.y, w1.w, acc);
        }
        #pragma unroll
        for (int o = 16; o; o >>= 1) acc += __shfl_down_sync(~0u, acc, o);
        if (!lane) wsum += g_z[g * VLD + row] * acc;    // g_z holds u
    }
    if (!lane) wp[wid] = wsum;
    __syncthreads();
    if (!tid) {
        float t2 = 0.f;
        #pragma unroll
        for (int w = 0; w < 8; w++) t2 += wp[w];
        g_cpart[s * 129 + bx] = t2;
    }
}

// ---------------- final deterministic sum -> d_out ----------------
__global__ void final_k(float* __restrict__ out) {
    __shared__ float ss[256];
    const int tid = threadIdx.x;
    float a = 0.f;
    for (int k = tid; k < SMAX * 129; k += 256) a += g_cpart[k];
    ss[tid] = a;
    __syncthreads();
    for (int o = 128; o; o >>= 1) { if (tid < o) ss[tid] += ss[tid + o]; __syncthreads(); }
    if (!tid) out[0] = 2.0f * ss[0];
}

extern "C" void kernel_launch(void* const* d_in, const int* in_sizes, int n_in,
                              void* d_out, int out_size) {
    (void)in_sizes; (void)n_in; (void)out_size;
    const float* X = (const float*)d_in[0];
    const int*   t = (const int*)d_in[1];

    partition_k<<<1, 256>>>(t);
    gather_k<<<(SMAX * NMAX * DDIM) / 256, 256>>>(X);
    norms_k<<<(SMAX * NMAX) / 8, 256>>>();

    gemm_k<<<dim3(32, 32, SMAX), 256>>>();
    reduce_k<<<SMAX, 256>>>();
    kbuild_k<<<dim3(NMAX + 1, SMAX), 256>>>();
    sinkhorn_k<<<NB, NTH>>>();
    contract_k<<<dim3(129, SMAX), 256>>>();
    final_k<<<1, 256>>>((float*)d_out);
}